// round 2
// baseline (speedup 1.0000x reference)
#include <cuda_runtime.h>
#include <cuda_bf16.h>

// Fused soft-VQ: out = softmax(-soft_rate * ||x - C||) @ C
// Flash-attention style single pass over the codebook (online softmax),
// SIMT fp32 baseline. N=32768, K=8192, D=256 (derived from in_sizes).

#define BM 64          // x rows per block
#define BN 64          // codebook entries per tile
#define DD 256         // feature dim
#define XS_STRIDE 260  // padded float stride for x/c tiles (bank-conflict avoidance)
#define SS_STRIDE 65   // padded stride for score tile

// shared layout (floats)
#define OFF_XS 0
#define OFF_CS (OFF_XS + BM * XS_STRIDE)           // 16640
#define OFF_SS (OFF_CS + BN * XS_STRIDE)           // 33280
#define OFF_X2 (OFF_SS + BM * SS_STRIDE)           // 37440
#define OFF_C2 (OFF_X2 + BM)
#define OFF_M  (OFF_C2 + BN)
#define OFF_L  (OFF_M + BM)
#define OFF_A  (OFF_L + BM)
#define SMEM_FLOATS (OFF_A + BM)                   // 37760
#define SMEM_BYTES (SMEM_FLOATS * 4)               // 151040

__global__ __launch_bounds__(256, 1)
void vq_soft_kernel(const float* __restrict__ x,
                    const float* __restrict__ cbk,
                    float* __restrict__ out,
                    int Ktot)
{
    extern __shared__ float sm[];
    float* xs   = sm + OFF_XS;
    float* cs   = sm + OFF_CS;
    float* ss   = sm + OFF_SS;
    float* x2   = sm + OFF_X2;
    float* c2   = sm + OFF_C2;
    float* mrow = sm + OFF_M;
    float* lrow = sm + OFF_L;
    float* arow = sm + OFF_A;

    const int tid  = threadIdx.x;
    const int row0 = blockIdx.x * BM;

    // ---- load x tile [BM, D] (float4, coalesced) ----
    for (int e = tid; e < BM * DD / 4; e += 256) {
        int r  = e >> 6;          // 64 float4 per row
        int c4 = e & 63;
        float4 v = ((const float4*)(x + (long long)(row0 + r) * DD))[c4];
        float* dst = xs + r * XS_STRIDE + c4 * 4;
        dst[0] = v.x; dst[1] = v.y; dst[2] = v.z; dst[3] = v.w;
    }
    __syncthreads();

    // ---- row norms + softmax state init ----
    if (tid < BM) {
        float s = 0.f;
        const float* xr = xs + tid * XS_STRIDE;
        #pragma unroll 8
        for (int k = 0; k < DD; k++) s += xr[k] * xr[k];
        x2[tid]   = s;
        mrow[tid] = -1e30f;
        lrow[tid] = 0.f;
    }

    // ---- O accumulator: thread (rg,cg) owns rows 4*rg..+3, cols 16*cg..+15 ----
    const int tr = tid >> 4, tc = tid & 15;   // S-GEMM mapping (4x4 tile)
    const int rg = tid >> 4, cg = tid & 15;   // O-GEMM mapping (4x16 tile)
    const int si = tid >> 2, sq4 = tid & 3;   // softmax mapping (row si, quarter)

    float o[4][16];
    #pragma unroll
    for (int r = 0; r < 4; r++)
        #pragma unroll
        for (int c = 0; c < 16; c++) o[r][c] = 0.f;

    const int nTiles = Ktot / BN;
    for (int kt = 0; kt < nTiles; kt++) {
        __syncthreads();   // protects cs/ss reuse from previous iteration

        // ---- load codebook tile [BN, D] ----
        const int col0 = kt * BN;
        for (int e = tid; e < BN * DD / 4; e += 256) {
            int r  = e >> 6;
            int c4 = e & 63;
            float4 v = ((const float4*)(cbk + (long long)(col0 + r) * DD))[c4];
            float* dst = cs + r * XS_STRIDE + c4 * 4;
            dst[0] = v.x; dst[1] = v.y; dst[2] = v.z; dst[3] = v.w;
        }
        __syncthreads();

        if (tid < BN) {
            float s = 0.f;
            const float* cr = cs + tid * XS_STRIDE;
            #pragma unroll 8
            for (int k = 0; k < DD; k++) s += cr[k] * cr[k];
            c2[tid] = s;
        }
        __syncthreads();

        // ---- S = x . c  (4x4 register tile per thread) ----
        float acc[4][4];
        #pragma unroll
        for (int a = 0; a < 4; a++)
            #pragma unroll
            for (int b = 0; b < 4; b++) acc[a][b] = 0.f;

        const float* xb  = xs + (4 * tr) * XS_STRIDE;
        const float* cb2 = cs + (4 * tc) * XS_STRIDE;
        #pragma unroll 4
        for (int k = 0; k < DD; k += 4) {
            float4 xv[4], cv[4];
            #pragma unroll
            for (int a = 0; a < 4; a++) xv[a] = *(const float4*)(xb + a * XS_STRIDE + k);
            #pragma unroll
            for (int b = 0; b < 4; b++) cv[b] = *(const float4*)(cb2 + b * XS_STRIDE + k);
            #pragma unroll
            for (int a = 0; a < 4; a++)
                #pragma unroll
                for (int b = 0; b < 4; b++)
                    acc[a][b] += xv[a].x * cv[b].x + xv[a].y * cv[b].y
                               + xv[a].z * cv[b].z + xv[a].w * cv[b].w;
        }

        // ---- epilogue: logits = -10 * sqrt(max(x2 + c2 - 2 dot, 0)) ----
        #pragma unroll
        for (int a = 0; a < 4; a++) {
            float xx = x2[4 * tr + a];
            #pragma unroll
            for (int b = 0; b < 4; b++) {
                float sqv = xx + c2[4 * tc + b] - 2.f * acc[a][b];
                sqv = fmaxf(sqv, 0.f);
                ss[(4 * tr + a) * SS_STRIDE + (4 * tc + b)] = -10.f * sqrtf(sqv);
            }
        }
        __syncthreads();

        // ---- online softmax update (4 threads per row, 16 cols each) ----
        {
            float* srw = ss + si * SS_STRIDE + sq4 * 16;
            float tmax = -1e30f;
            #pragma unroll
            for (int j = 0; j < 16; j++) tmax = fmaxf(tmax, srw[j]);
            tmax = fmaxf(tmax, __shfl_xor_sync(0xffffffffu, tmax, 1));
            tmax = fmaxf(tmax, __shfl_xor_sync(0xffffffffu, tmax, 2));
            const float mold = mrow[si];
            const float newm = fmaxf(mold, tmax);
            float psum = 0.f;
            #pragma unroll
            for (int j = 0; j < 16; j++) {
                float p = __expf(srw[j] - newm);
                srw[j] = p;
                psum += p;
            }
            psum += __shfl_xor_sync(0xffffffffu, psum, 1);
            psum += __shfl_xor_sync(0xffffffffu, psum, 2);
            if (sq4 == 0) {
                float alpha = __expf(mold - newm);
                lrow[si] = lrow[si] * alpha + psum;
                mrow[si] = newm;
                arow[si] = alpha;
            }
        }
        __syncthreads();

        // ---- O = O*alpha + P @ C_tile  (4 rows x 16 cols per thread) ----
        {
            float al[4];
            #pragma unroll
            for (int r = 0; r < 4; r++) al[r] = arow[4 * rg + r];
            #pragma unroll
            for (int r = 0; r < 4; r++)
                #pragma unroll
                for (int c = 0; c < 16; c++) o[r][c] *= al[r];

            #pragma unroll 4
            for (int j = 0; j < BN; j++) {
                float p[4];
                #pragma unroll
                for (int r = 0; r < 4; r++) p[r] = ss[(4 * rg + r) * SS_STRIDE + j];
                const float* crow = cs + j * XS_STRIDE + cg * 16;
                float cvv[16];
                #pragma unroll
                for (int c = 0; c < 16; c += 4) {
                    float4 v = *(const float4*)(crow + c);
                    cvv[c] = v.x; cvv[c + 1] = v.y; cvv[c + 2] = v.z; cvv[c + 3] = v.w;
                }
                #pragma unroll
                for (int r = 0; r < 4; r++)
                    #pragma unroll
                    for (int c = 0; c < 16; c++)
                        o[r][c] += p[r] * cvv[c];
            }
        }
    }
    __syncthreads();

    // ---- finalize: out = O / l ----
    #pragma unroll
    for (int r = 0; r < 4; r++) {
        float inv = 1.f / lrow[4 * rg + r];
        float* orow = out + (long long)(row0 + 4 * rg + r) * DD + cg * 16;
        #pragma unroll
        for (int c = 0; c < 16; c += 4) {
            float4 v;
            v.x = o[r][c] * inv;
            v.y = o[r][c + 1] * inv;
            v.z = o[r][c + 2] * inv;
            v.w = o[r][c + 3] * inv;
            *(float4*)(orow + c) = v;
        }
    }
}

// Fill possible tail of d_out (the reference's second tuple element, -1)
__global__ void fill_tail_kernel(float* p, long long n)
{
    long long i = (long long)blockIdx.x * blockDim.x + threadIdx.x;
    if (i < n) p[i] = -1.0f;
}

extern "C" void kernel_launch(void* const* d_in, const int* in_sizes, int n_in,
                              void* d_out, int out_size)
{
    const float* x   = (const float*)d_in[0];
    const float* cbk = (const float*)d_in[1];
    float* out = (float*)d_out;

    const int N = in_sizes[0] / DD;   // 32768
    const int K = in_sizes[1] / DD;   // 8192

    cudaFuncSetAttribute(vq_soft_kernel,
                         cudaFuncAttributeMaxDynamicSharedMemorySize, SMEM_BYTES);

    dim3 grid(N / BM);
    vq_soft_kernel<<<grid, 256, SMEM_BYTES>>>(x, cbk, out, K);

    long long nd = (long long)N * DD;
    if ((long long)out_size > nd) {
        long long tail = (long long)out_size - nd;
        int thr = 256;
        int blocks = (int)((tail + thr - 1) / thr);
        fill_tail_kernel<<<blocks, thr>>>(out + nd, tail);
    }
}